// round 3
// baseline (speedup 1.0000x reference)
#include <cuda_runtime.h>
#include <math.h>
#include <stdint.h>

#define B_ 16
#define N_ 1024
#define C_ 256

// fma.rn.f32x2: packed 2-lane fp32 FMA (Blackwell). d = a*b + c lane-wise.
__device__ __forceinline__ void ffma2(unsigned long long& acc,
                                      unsigned long long a,
                                      unsigned long long b) {
    asm("fma.rn.f32x2 %0, %1, %2, %0;" : "+l"(acc) : "l"(a), "l"(b));
}

__device__ __forceinline__ void lds_v2u64(unsigned long long& x,
                                          unsigned long long& y,
                                          uint32_t addr) {
    asm("ld.shared.v2.u64 {%0, %1}, [%2];" : "=l"(x), "=l"(y) : "r"(addr));
}

__device__ __forceinline__ void sts_dup2(uint32_t addr, float v) {
    asm volatile("st.shared.v2.f32 [%0], {%1, %1};" :: "r"(addr), "f"(v));
}

__device__ __forceinline__ float lo_of(unsigned long long u) {
    return __uint_as_float((uint32_t)(u & 0xffffffffull));
}
__device__ __forceinline__ float hi_of(unsigned long long u) {
    return __uint_as_float((uint32_t)(u >> 32));
}

// 16B-chunk swizzle for the B-operand tile: chunk c (0..31) -> c ^ (c>>3)
__device__ __forceinline__ uint32_t swz(uint32_t c) { return c ^ (c >> 3); }

// ---------------------------------------------------------------------------
// Kernel 1: attn = masked((Q K^T + dis) / 16). 128x128 tile, 256 thr, 8x8/thr.
// A (Q) dup-layout in smem, B (K) swizzled; inner loop on fma.rn.f32x2.
// ---------------------------------------------------------------------------
__global__ __launch_bounds__(256) void qk_scores_kernel(
    const float* __restrict__ Q,
    const float* __restrict__ K,
    const float* __restrict__ dis,
    const int*   __restrict__ mask,
    float* __restrict__ attn)
{
    __shared__ float Qs[16 * 256];   // [cc][2*r] dup pairs, stride 256 floats
    __shared__ float Ks[16 * 128];   // [cc][col] swizzled 16B chunks, stride 128

    const int b     = blockIdx.z;
    const int qBase = blockIdx.y * 128;
    const int kBase = blockIdx.x * 128;

    const float* Qb = Q + (size_t)b * N_ * C_;
    const float* Kb = K + (size_t)b * N_ * C_;

    const int tx  = threadIdx.x;   // 0..15
    const int ty  = threadIdx.y;   // 0..15
    const int tid = ty * 16 + tx;

    const uint32_t qs0 = (uint32_t)__cvta_generic_to_shared(Qs);
    const uint32_t ks0 = (uint32_t)__cvta_generic_to_shared(Ks);

    unsigned long long acc[8][4];
#pragma unroll
    for (int i = 0; i < 8; i++)
#pragma unroll
        for (int p = 0; p < 4; p++) acc[i][p] = 0ull;

    for (int c0 = 0; c0 < C_; c0 += 16) {
#pragma unroll
        for (int e = 0; e < 2; e++) {
            int linear = tid + e * 256;
            int r  = linear >> 2;
            int c4 = (linear & 3) * 4;
            float4 vq = *reinterpret_cast<const float4*>(
                &Qb[(size_t)(qBase + r) * C_ + c0 + c4]);
            float4 vk = *reinterpret_cast<const float4*>(
                &Kb[(size_t)(kBase + r) * C_ + c0 + c4]);
            // Q dup: Qs[c4+d][2r], [2r+1] = vq[d]
            uint32_t qa = qs0 + (uint32_t)(c4 * 1024 + r * 8);
            sts_dup2(qa,          vq.x);
            sts_dup2(qa + 1024,   vq.y);
            sts_dup2(qa + 2048,   vq.z);
            sts_dup2(qa + 3072,   vq.w);
            // K: Ks[c4+d][r] with chunk swizzle
            uint32_t chunk = (uint32_t)(r >> 2);
            uint32_t off   = swz(chunk) * 16 + (uint32_t)(r & 3) * 4;
            float kv[4] = {vk.x, vk.y, vk.z, vk.w};
#pragma unroll
            for (int d = 0; d < 4; d++) {
                uint32_t ka = ks0 + (uint32_t)((c4 + d) * 512) + off;
                asm volatile("st.shared.f32 [%0], %1;" :: "r"(ka), "f"(kv[d]));
            }
        }
        __syncthreads();

#pragma unroll
        for (int cc = 0; cc < 16; cc++) {
            unsigned long long a[8], bb[4];
            uint32_t abase = qs0 + (uint32_t)(cc * 1024 + ty * 64);
            lds_v2u64(a[0], a[1], abase);
            lds_v2u64(a[2], a[3], abase + 16);
            lds_v2u64(a[4], a[5], abase + 32);
            lds_v2u64(a[6], a[7], abase + 48);
            uint32_t bbase = ks0 + (uint32_t)(cc * 512);
            lds_v2u64(bb[0], bb[1], bbase + swz(2 * tx)     * 16);
            lds_v2u64(bb[2], bb[3], bbase + swz(2 * tx + 1) * 16);
#pragma unroll
            for (int i = 0; i < 8; i++)
#pragma unroll
                for (int p = 0; p < 4; p++)
                    ffma2(acc[i][p], a[i], bb[p]);
        }
        __syncthreads();
    }

    // Epilogue: cols k = kBase + tx*8 + 0..7, rows q = qBase + ty*8 + i
#pragma unroll
    for (int i = 0; i < 8; i++) {
        int q = qBase + ty * 8 + i;
        size_t rowb = ((size_t)b * N_ + q) * N_ + kBase + tx * 8;
        float4 d0 = *reinterpret_cast<const float4*>(&dis[rowb]);
        float4 d1 = *reinterpret_cast<const float4*>(&dis[rowb + 4]);
        int4   m0 = *reinterpret_cast<const int4*>(&mask[rowb]);
        int4   m1 = *reinterpret_cast<const int4*>(&mask[rowb + 4]);
        float4 o0, o1;
        o0.x = m0.x ? -INFINITY : (lo_of(acc[i][0]) + d0.x) * 0.0625f;
        o0.y = m0.y ? -INFINITY : (hi_of(acc[i][0]) + d0.y) * 0.0625f;
        o0.z = m0.z ? -INFINITY : (lo_of(acc[i][1]) + d0.z) * 0.0625f;
        o0.w = m0.w ? -INFINITY : (hi_of(acc[i][1]) + d0.w) * 0.0625f;
        o1.x = m1.x ? -INFINITY : (lo_of(acc[i][2]) + d1.x) * 0.0625f;
        o1.y = m1.y ? -INFINITY : (hi_of(acc[i][2]) + d1.y) * 0.0625f;
        o1.z = m1.z ? -INFINITY : (lo_of(acc[i][3]) + d1.z) * 0.0625f;
        o1.w = m1.w ? -INFINITY : (hi_of(acc[i][3]) + d1.w) * 0.0625f;
        *reinterpret_cast<float4*>(&attn[rowb])     = o0;
        *reinterpret_cast<float4*>(&attn[rowb + 4]) = o1;
    }
}

// ---------------------------------------------------------------------------
// Kernel 2: in-place row softmax (rows of 1024). One block per row.
// ---------------------------------------------------------------------------
__global__ __launch_bounds__(256) void softmax_kernel(float* __restrict__ attn)
{
    __shared__ float red[256];
    const size_t base = (size_t)blockIdx.x * N_;
    const int t = threadIdx.x;

    float v[4];
#pragma unroll
    for (int e = 0; e < 4; e++) v[e] = attn[base + t + e * 256];

    float m = fmaxf(fmaxf(v[0], v[1]), fmaxf(v[2], v[3]));
    red[t] = m;
    __syncthreads();
#pragma unroll
    for (int s = 128; s >= 1; s >>= 1) {
        if (t < s) red[t] = fmaxf(red[t], red[t + s]);
        __syncthreads();
    }
    m = red[0];
    __syncthreads();

    float p[4], lsum = 0.0f;
#pragma unroll
    for (int e = 0; e < 4; e++) {
        p[e] = __expf(v[e] - m);
        lsum += p[e];
    }
    red[t] = lsum;
    __syncthreads();
#pragma unroll
    for (int s = 128; s >= 1; s >>= 1) {
        if (t < s) red[t] += red[t + s];
        __syncthreads();
    }
    float inv = 1.0f / red[0];

#pragma unroll
    for (int e = 0; e < 4; e++) attn[base + t + e * 256] = p[e] * inv;
}

// ---------------------------------------------------------------------------
// Kernel 3: p_val = p_attn @ V. Same f32x2 structure; A=P (dup), B=V (swizzle).
// ---------------------------------------------------------------------------
__global__ __launch_bounds__(256) void pv_kernel(
    const float* __restrict__ P,
    const float* __restrict__ V,
    float* __restrict__ out)
{
    __shared__ float Ps[16 * 256];   // [kk][2*q] dup pairs
    __shared__ float Vs[16 * 128];   // [kk][c] swizzled chunks

    const int b     = blockIdx.z;
    const int qBase = blockIdx.y * 128;
    const int cBase = blockIdx.x * 128;

    const float* Pb = P + (size_t)b * N_ * N_;
    const float* Vb = V + (size_t)b * N_ * C_;

    const int tx  = threadIdx.x;
    const int ty  = threadIdx.y;
    const int tid = ty * 16 + tx;

    const uint32_t ps0 = (uint32_t)__cvta_generic_to_shared(Ps);
    const uint32_t vs0 = (uint32_t)__cvta_generic_to_shared(Vs);

    unsigned long long acc[8][4];
#pragma unroll
    for (int i = 0; i < 8; i++)
#pragma unroll
        for (int p = 0; p < 4; p++) acc[i][p] = 0ull;

    for (int k0 = 0; k0 < N_; k0 += 16) {
        // P tile: 128 q x 16 k -> dup-transposed
#pragma unroll
        for (int e = 0; e < 2; e++) {
            int linear = tid + e * 256;
            int q  = linear >> 2;
            int k4 = (linear & 3) * 4;
            float4 vp = *reinterpret_cast<const float4*>(
                &Pb[(size_t)(qBase + q) * N_ + k0 + k4]);
            uint32_t pa = ps0 + (uint32_t)(k4 * 1024 + q * 8);
            sts_dup2(pa,        vp.x);
            sts_dup2(pa + 1024, vp.y);
            sts_dup2(pa + 2048, vp.z);
            sts_dup2(pa + 3072, vp.w);
        }
        // V tile: 16 k x 128 c -> direct rows, swizzled 16B chunks
#pragma unroll
        for (int e = 0; e < 2; e++) {
            int linear = tid + e * 256;
            int k  = linear >> 5;          // 0..15
            int cq = linear & 31;          // chunk 0..31
            float4 vv = *reinterpret_cast<const float4*>(
                &Vb[(size_t)(k0 + k) * C_ + cBase + cq * 4]);
            uint32_t va = vs0 + (uint32_t)(k * 512) + swz((uint32_t)cq) * 16;
            asm volatile("st.shared.v4.f32 [%0], {%1, %2, %3, %4};"
                         :: "r"(va), "f"(vv.x), "f"(vv.y), "f"(vv.z), "f"(vv.w));
        }
        __syncthreads();

#pragma unroll
        for (int kk = 0; kk < 16; kk++) {
            unsigned long long a[8], bb[4];
            uint32_t abase = ps0 + (uint32_t)(kk * 1024 + ty * 64);
            lds_v2u64(a[0], a[1], abase);
            lds_v2u64(a[2], a[3], abase + 16);
            lds_v2u64(a[4], a[5], abase + 32);
            lds_v2u64(a[6], a[7], abase + 48);
            uint32_t bbase = vs0 + (uint32_t)(kk * 512);
            lds_v2u64(bb[0], bb[1], bbase + swz(2 * tx)     * 16);
            lds_v2u64(bb[2], bb[3], bbase + swz(2 * tx + 1) * 16);
#pragma unroll
            for (int i = 0; i < 8; i++)
#pragma unroll
                for (int p = 0; p < 4; p++)
                    ffma2(acc[i][p], a[i], bb[p]);
        }
        __syncthreads();
    }

#pragma unroll
    for (int i = 0; i < 8; i++) {
        int q = qBase + ty * 8 + i;
        size_t rowb = ((size_t)b * N_ + q) * C_ + cBase + tx * 8;
        float4 o0, o1;
        o0.x = lo_of(acc[i][0]); o0.y = hi_of(acc[i][0]);
        o0.z = lo_of(acc[i][1]); o0.w = hi_of(acc[i][1]);
        o1.x = lo_of(acc[i][2]); o1.y = hi_of(acc[i][2]);
        o1.z = lo_of(acc[i][3]); o1.w = hi_of(acc[i][3]);
        *reinterpret_cast<float4*>(&out[rowb])     = o0;
        *reinterpret_cast<float4*>(&out[rowb + 4]) = o1;
    }
}

// ---------------------------------------------------------------------------
// Launch
// ---------------------------------------------------------------------------
extern "C" void kernel_launch(void* const* d_in, const int* in_sizes, int n_in,
                              void* d_out, int out_size)
{
    const float* Q    = (const float*)d_in[0];
    const float* K    = (const float*)d_in[1];
    const float* V    = (const float*)d_in[2];
    const int*   mask = (const int*)d_in[3];
    const float* dis  = (const float*)d_in[4];

    float* out    = (float*)d_out;
    float* p_val  = out;                          // [B, N, C]
    float* p_attn = out + (size_t)B_ * N_ * C_;   // [B, N, N]

    dim3 blk(16, 16);
    qk_scores_kernel<<<dim3(N_ / 128, N_ / 128, B_), blk>>>(Q, K, dis, mask, p_attn);
    softmax_kernel<<<B_ * N_, 256>>>(p_attn);
    pv_kernel<<<dim3(C_ / 128, N_ / 128, B_), blk>>>(p_attn, V, p_val);
}

// round 4
// speedup vs baseline: 1.4803x; 1.4803x over previous
#include <cuda_runtime.h>
#include <math.h>
#include <stdint.h>

#define B_ 16
#define N_ 1024
#define C_ 256

#define KC  16     // k-chunk per smem tile
#define PAD 20     // smem row stride (floats): (r*20+c)%32 covers all banks

// ---------------------------------------------------------------------------
// mma.sync m16n8k8 tf32, row.col, fp32 accumulate
// ---------------------------------------------------------------------------
__device__ __forceinline__ void mma_tf32(float* d,
                                         uint32_t a0, uint32_t a1,
                                         uint32_t a2, uint32_t a3,
                                         uint32_t b0, uint32_t b1) {
    asm volatile(
        "mma.sync.aligned.m16n8k8.row.col.f32.tf32.tf32.f32 "
        "{%0,%1,%2,%3}, {%4,%5,%6,%7}, {%8,%9}, {%0,%1,%2,%3};"
        : "+f"(d[0]), "+f"(d[1]), "+f"(d[2]), "+f"(d[3])
        : "r"(a0), "r"(a1), "r"(a2), "r"(a3), "r"(b0), "r"(b1));
}

// split x = hi + lo, hi has tf32-representable mantissa (top 10 bits)
__device__ __forceinline__ void split_tf32(float x, float& h, float& l) {
    h = __uint_as_float(__float_as_uint(x) & 0xFFFFE000u);
    l = x - h;
}

__device__ __forceinline__ uint32_t f2u(float x) { return __float_as_uint(x); }

// ---------------------------------------------------------------------------
// Kernel 1: attn = masked((Q K^T + dis) * 0.0625). 128x128 tile, 8 warps.
// Warp tile 64x32 (2x4 warp grid), 4x4 m16n8 tiles per warp, 3xTF32.
// ---------------------------------------------------------------------------
__global__ __launch_bounds__(256, 2) void qk_scores_kernel(
    const float* __restrict__ Q,
    const float* __restrict__ K,
    const float* __restrict__ dis,
    const int*   __restrict__ mask,
    float* __restrict__ attn)
{
    __shared__ float Ah[128 * PAD], Al[128 * PAD];
    __shared__ float Bh[128 * PAD], Bl[128 * PAD];

    const int b     = blockIdx.z;
    const int qBase = blockIdx.y * 128;
    const int kBase = blockIdx.x * 128;

    const float* Qb = Q + (size_t)b * N_ * C_;
    const float* Kb = K + (size_t)b * N_ * C_;

    const int tid  = threadIdx.x;
    const int lane = tid & 31;
    const int w    = tid >> 5;      // 0..7
    const int wm   = w >> 2;        // 0..1  (64 rows each)
    const int wn   = w & 3;         // 0..3  (32 cols each)
    const int g    = lane >> 2;     // groupID 0..7
    const int cq   = lane & 3;      // threadID-in-group 0..3

    float acc[4][4][4];
#pragma unroll
    for (int i = 0; i < 4; i++)
#pragma unroll
        for (int j = 0; j < 4; j++)
#pragma unroll
            for (int r = 0; r < 4; r++) acc[i][j][r] = 0.0f;

    for (int c0 = 0; c0 < C_; c0 += KC) {
        // cooperative load: A=Q tile 128xKC, B=K tile 128xKC (both row-major)
#pragma unroll
        for (int e = 0; e < 2; e++) {
            int lin = tid + e * 256;
            int row = lin >> 2;
            int c4  = (lin & 3) * 4;
            float4 vq = *reinterpret_cast<const float4*>(
                &Qb[(size_t)(qBase + row) * C_ + c0 + c4]);
            float4 vk = *reinterpret_cast<const float4*>(
                &Kb[(size_t)(kBase + row) * C_ + c0 + c4]);
            float4 qh, ql, kh, kl;
            split_tf32(vq.x, qh.x, ql.x); split_tf32(vq.y, qh.y, ql.y);
            split_tf32(vq.z, qh.z, ql.z); split_tf32(vq.w, qh.w, ql.w);
            split_tf32(vk.x, kh.x, kl.x); split_tf32(vk.y, kh.y, kl.y);
            split_tf32(vk.z, kh.z, kl.z); split_tf32(vk.w, kh.w, kl.w);
            int sidx = row * PAD + c4;
            *reinterpret_cast<float4*>(&Ah[sidx]) = qh;
            *reinterpret_cast<float4*>(&Al[sidx]) = ql;
            *reinterpret_cast<float4*>(&Bh[sidx]) = kh;
            *reinterpret_cast<float4*>(&Bl[sidx]) = kl;
        }
        __syncthreads();

#pragma unroll
        for (int s = 0; s < KC; s += 8) {
            uint32_t ah[4][4], al[4][4];
#pragma unroll
            for (int i = 0; i < 4; i++) {
                int idx = (wm * 64 + i * 16 + g) * PAD + s + cq;
                ah[i][0] = f2u(Ah[idx]);
                ah[i][1] = f2u(Ah[idx + 8 * PAD]);
                ah[i][2] = f2u(Ah[idx + 4]);
                ah[i][3] = f2u(Ah[idx + 8 * PAD + 4]);
                al[i][0] = f2u(Al[idx]);
                al[i][1] = f2u(Al[idx + 8 * PAD]);
                al[i][2] = f2u(Al[idx + 4]);
                al[i][3] = f2u(Al[idx + 8 * PAD + 4]);
            }
#pragma unroll
            for (int j = 0; j < 4; j++) {
                int bidx = (wn * 32 + j * 8 + g) * PAD + s + cq;
                uint32_t bh0 = f2u(Bh[bidx]), bh1 = f2u(Bh[bidx + 4]);
                uint32_t bl0 = f2u(Bl[bidx]), bl1 = f2u(Bl[bidx + 4]);
#pragma unroll
                for (int i = 0; i < 4; i++) {
                    mma_tf32(acc[i][j], ah[i][0], ah[i][1], ah[i][2], ah[i][3], bh0, bh1);
                    mma_tf32(acc[i][j], al[i][0], al[i][1], al[i][2], al[i][3], bh0, bh1);
                    mma_tf32(acc[i][j], ah[i][0], ah[i][1], ah[i][2], ah[i][3], bl0, bl1);
                }
            }
        }
        __syncthreads();
    }

    // epilogue: add dis, scale, mask -> attn
#pragma unroll
    for (int i = 0; i < 4; i++) {
        int r0 = qBase + wm * 64 + i * 16 + g;
        int r1 = r0 + 8;
#pragma unroll
        for (int j = 0; j < 4; j++) {
            int col = kBase + wn * 32 + j * 8 + 2 * cq;
            size_t i0 = ((size_t)b * N_ + r0) * N_ + col;
            size_t i1 = ((size_t)b * N_ + r1) * N_ + col;
            float2 d0 = *reinterpret_cast<const float2*>(&dis[i0]);
            float2 d1 = *reinterpret_cast<const float2*>(&dis[i1]);
            int2   m0 = *reinterpret_cast<const int2*>(&mask[i0]);
            int2   m1 = *reinterpret_cast<const int2*>(&mask[i1]);
            float2 o0, o1;
            o0.x = m0.x ? -INFINITY : (acc[i][j][0] + d0.x) * 0.0625f;
            o0.y = m0.y ? -INFINITY : (acc[i][j][1] + d0.y) * 0.0625f;
            o1.x = m1.x ? -INFINITY : (acc[i][j][2] + d1.x) * 0.0625f;
            o1.y = m1.y ? -INFINITY : (acc[i][j][3] + d1.y) * 0.0625f;
            *reinterpret_cast<float2*>(&attn[i0]) = o0;
            *reinterpret_cast<float2*>(&attn[i1]) = o1;
        }
    }
}

// ---------------------------------------------------------------------------
// Kernel 2: in-place row softmax (rows of 1024). One block per row.
// ---------------------------------------------------------------------------
__global__ __launch_bounds__(256) void softmax_kernel(float* __restrict__ attn)
{
    __shared__ float red[256];
    const size_t base = (size_t)blockIdx.x * N_;
    const int t = threadIdx.x;

    float v[4];
#pragma unroll
    for (int e = 0; e < 4; e++) v[e] = attn[base + t + e * 256];

    float m = fmaxf(fmaxf(v[0], v[1]), fmaxf(v[2], v[3]));
    red[t] = m;
    __syncthreads();
#pragma unroll
    for (int s = 128; s >= 1; s >>= 1) {
        if (t < s) red[t] = fmaxf(red[t], red[t + s]);
        __syncthreads();
    }
    m = red[0];
    __syncthreads();

    float p[4], lsum = 0.0f;
#pragma unroll
    for (int e = 0; e < 4; e++) {
        p[e] = __expf(v[e] - m);
        lsum += p[e];
    }
    red[t] = lsum;
    __syncthreads();
#pragma unroll
    for (int s = 128; s >= 1; s >>= 1) {
        if (t < s) red[t] += red[t + s];
        __syncthreads();
    }
    float inv = 1.0f / red[0];

#pragma unroll
    for (int e = 0; e < 4; e++) attn[base + t + e * 256] = p[e] * inv;
}

// ---------------------------------------------------------------------------
// Kernel 3: p_val = p_attn @ V. Same mma structure; B=V transposed into smem.
// ---------------------------------------------------------------------------
__global__ __launch_bounds__(256, 2) void pv_kernel(
    const float* __restrict__ P,
    const float* __restrict__ V,
    float* __restrict__ out)
{
    __shared__ float Ah[128 * PAD], Al[128 * PAD];
    __shared__ float Bh[128 * PAD], Bl[128 * PAD];

    const int b     = blockIdx.z;
    const int qBase = blockIdx.y * 128;
    const int nBase = blockIdx.x * 128;

    const float* Pb = P + (size_t)b * N_ * N_;
    const float* Vb = V + (size_t)b * N_ * C_;

    const int tid  = threadIdx.x;
    const int lane = tid & 31;
    const int w    = tid >> 5;
    const int wm   = w >> 2;
    const int wn   = w & 3;
    const int g    = lane >> 2;
    const int cq   = lane & 3;

    float acc[4][4][4];
#pragma unroll
    for (int i = 0; i < 4; i++)
#pragma unroll
        for (int j = 0; j < 4; j++)
#pragma unroll
            for (int r = 0; r < 4; r++) acc[i][j][r] = 0.0f;

    // B-transpose load mapping: n = tid&127, kk = (tid>>7)*8 + u
    const int nIdx = tid & 127;
    const int kh   = tid >> 7;

    for (int k0 = 0; k0 < N_; k0 += KC) {
        // A = P tile 128xKC row-major
#pragma unroll
        for (int e = 0; e < 2; e++) {
            int lin = tid + e * 256;
            int row = lin >> 2;
            int c4  = (lin & 3) * 4;
            float4 vp = *reinterpret_cast<const float4*>(
                &Pb[(size_t)(qBase + row) * N_ + k0 + c4]);
            float4 ph, pl;
            split_tf32(vp.x, ph.x, pl.x); split_tf32(vp.y, ph.y, pl.y);
            split_tf32(vp.z, ph.z, pl.z); split_tf32(vp.w, ph.w, pl.w);
            int sidx = row * PAD + c4;
            *reinterpret_cast<float4*>(&Ah[sidx]) = ph;
            *reinterpret_cast<float4*>(&Al[sidx]) = pl;
        }
        // B = V tile KCx128 -> transposed into Bs[n][k]
#pragma unroll
        for (int u = 0; u < 8; u++) {
            int kk = kh * 8 + u;
            float v = Vb[(size_t)(k0 + kk) * C_ + nBase + nIdx];
            float h, l;
            split_tf32(v, h, l);
            Bh[nIdx * PAD + kk] = h;
            Bl[nIdx * PAD + kk] = l;
        }
        __syncthreads();

#pragma unroll
        for (int s = 0; s < KC; s += 8) {
            uint32_t ah[4][4], al[4][4];
#pragma unroll
            for (int i = 0; i < 4; i++) {
                int idx = (wm * 64 + i * 16 + g) * PAD + s + cq;
                ah[i][0] = f2u(Ah[idx]);
                ah[i][1] = f2u(Ah[idx + 8 * PAD]);
                ah[i][2] = f2u(Ah[idx + 4]);
                ah[i][3] = f2u(Ah[idx + 8 * PAD + 4]);
                al[i][0] = f2u(Al[idx]);
                al[i][1] = f2u(Al[idx + 8 * PAD]);
                al[i][2] = f2u(Al[idx + 4]);
                al[i][3] = f2u(Al[idx + 8 * PAD + 4]);
            }
#pragma unroll
            for (int j = 0; j < 4; j++) {
                int bidx = (wn * 32 + j * 8 + g) * PAD + s + cq;
                uint32_t bh0 = f2u(Bh[bidx]), bh1 = f2u(Bh[bidx + 4]);
                uint32_t bl0 = f2u(Bl[bidx]), bl1 = f2u(Bl[bidx + 4]);
#pragma unroll
                for (int i = 0; i < 4; i++) {
                    mma_tf32(acc[i][j], ah[i][0], ah[i][1], ah[i][2], ah[i][3], bh0, bh1);
                    mma_tf32(acc[i][j], al[i][0], al[i][1], al[i][2], al[i][3], bh0, bh1);
                    mma_tf32(acc[i][j], ah[i][0], ah[i][1], ah[i][2], ah[i][3], bl0, bl1);
                }
            }
        }
        __syncthreads();
    }

#pragma unroll
    for (int i = 0; i < 4; i++) {
        int r0 = qBase + wm * 64 + i * 16 + g;
        int r1 = r0 + 8;
#pragma unroll
        for (int j = 0; j < 4; j++) {
            int col = nBase + wn * 32 + j * 8 + 2 * cq;
            size_t i0 = ((size_t)b * N_ + r0) * C_ + col;
            size_t i1 = ((size_t)b * N_ + r1) * C_ + col;
            float2 o0, o1;
            o0.x = acc[i][j][0]; o0.y = acc[i][j][1];
            o1.x = acc[i][j][2]; o1.y = acc[i][j][3];
            *reinterpret_cast<float2*>(&out[i0]) = o0;
            *reinterpret_cast<float2*>(&out[i1]) = o1;
        }
    }
}

// ---------------------------------------------------------------------------
// Launch
// ---------------------------------------------------------------------------
extern "C" void kernel_launch(void* const* d_in, const int* in_sizes, int n_in,
                              void* d_out, int out_size)
{
    const float* Q    = (const float*)d_in[0];
    const float* K    = (const float*)d_in[1];
    const float* V    = (const float*)d_in[2];
    const int*   mask = (const int*)d_in[3];
    const float* dis  = (const float*)d_in[4];

    float* out    = (float*)d_out;
    float* p_val  = out;                          // [B, N, C]
    float* p_attn = out + (size_t)B_ * N_ * C_;   // [B, N, N]

    qk_scores_kernel<<<dim3(N_ / 128, N_ / 128, B_), 256>>>(Q, K, dis, mask, p_attn);
    softmax_kernel<<<B_ * N_, 256>>>(p_attn);
    pv_kernel<<<dim3(C_ / 128, N_ / 128, B_), 256>>>(p_attn, V, p_val);
}